// round 2
// baseline (speedup 1.0000x reference)
#include <cuda_runtime.h>
#include <cuda_fp16.h>
#include <cstdint>

#define M_DIM 8192
#define K_DIM 4096
#define N_DIM 11008

// ---------------- scratch (device globals; no runtime allocation) ----------
__device__ __half g_Ah[(size_t)M_DIM * K_DIM];   // A in fp16, [M, K] row-major
__device__ __half g_Wt[(size_t)N_DIM * K_DIM];   // W^T dequant fp16, [N, K] row-major

// ---------------- pre-pass 1: A fp32 -> fp16 -------------------------------
__global__ void convert_a_kernel(const float* __restrict__ a) {
    size_t i = (size_t)blockIdx.x * blockDim.x + threadIdx.x;   // float4 index
    float4 v = reinterpret_cast<const float4*>(a)[i];
    __half2 h0 = __floats2half2_rn(v.x, v.y);
    __half2 h1 = __floats2half2_rn(v.z, v.w);
    uint2 o;
    o.x = *reinterpret_cast<uint32_t*>(&h0);
    o.y = *reinterpret_cast<uint32_t*>(&h1);
    reinterpret_cast<uint2*>(g_Ah)[i] = o;
}

// ---------------- pre-pass 2: int4 dequant + transpose to Wt[N,K] ----------
// grid (K/64, N/32), block 256. Each block: 64 k (32 packed rows) x 32 n.
__global__ void dequant_w_kernel(const int* __restrict__ w, const float* __restrict__ scale,
                                 const int* __restrict__ zp) {
    __shared__ int sw[32][33];
    __shared__ float ssc[32];
    __shared__ float szp[32];
    int kt = blockIdx.x;               // 0..63 (64 k per tile; within one group: 128 = 2*64)
    int nt = blockIdx.y;               // 0..343
    int kp0 = kt * 32, n0 = nt * 32;
    int g = kt >> 1;
    int t = threadIdx.x;
    for (int i = t; i < 1024; i += 256) {
        int r = i >> 5, c = i & 31;
        sw[r][c] = w[(size_t)(kp0 + r) * N_DIM + (n0 + c)];
    }
    if (t < 32) {
        ssc[t] = scale[(size_t)g * N_DIM + n0 + t];
        szp[t] = (float)zp[(size_t)g * N_DIM + n0 + t];
    }
    __syncthreads();
    int nl = t >> 3;            // local n 0..31
    int kq = (t & 7) * 4;       // local packed-row start (4 packed rows = 8 k)
    float sc = ssc[nl], z = szp[nl];
    __half2 outv[4];
#pragma unroll
    for (int j = 0; j < 4; j++) {
        int wv = sw[kq + j][nl];
        outv[j] = __floats2half2_rn(((float)(wv & 0xF) - z) * sc,         // k even (low nibble)
                                    ((float)((wv >> 4) & 0xF) - z) * sc); // k odd  (high nibble)
    }
    size_t off = (size_t)(n0 + nl) * K_DIM + (size_t)kt * 64 + kq * 2;
    *reinterpret_cast<float4*>(&g_Wt[off]) = *reinterpret_cast<float4*>(outv);
}

// ---------------- main GEMM: mma.sync m16n8k16, cp.async pipeline ----------
// Non-'a' PTX only (harness lowers through compute_103 which bars tcgen05/TMA).
static constexpr int BM = 128, BN = 128, BK = 32, STAGES = 4;
static constexpr int ROW_HALFS = 40;                 // 32 data + 8 pad -> 80B row stride
static constexpr int ROW_BYTES = ROW_HALFS * 2;      // 80
static constexpr int TILE_STAGE_BYTES = 128 * ROW_BYTES;          // 10240 per operand per stage
static constexpr int SB_OFF = STAGES * TILE_STAGE_BYTES;          // B tiles after A tiles
static constexpr int GEMM_SMEM = 2 * STAGES * TILE_STAGE_BYTES;   // 81920
static constexpr int TM_TILES = M_DIM / BM;   // 64
static constexpr int TN_TILES = N_DIM / BN;   // 86
static constexpr int KITERS = K_DIM / BK;     // 128

__device__ __forceinline__ uint32_t smem_u32(const void* p) {
    uint32_t a;
    asm("{ .reg .u64 t; cvta.to.shared.u64 t, %1; cvt.u32.u64 %0, t; }" : "=r"(a) : "l"(p));
    return a;
}

#define CP_ASYNC_16(dst, src) \
    asm volatile("cp.async.cg.shared.global [%0], [%1], 16;" :: "r"(dst), "l"(src))
#define CP_ASYNC_COMMIT() asm volatile("cp.async.commit_group;")
#define CP_ASYNC_WAIT2()  asm volatile("cp.async.wait_group 2;")

#define LDSM_X4(r0, r1, r2, r3, addr) \
    asm volatile("ldmatrix.sync.aligned.m8n8.x4.shared.b16 {%0,%1,%2,%3}, [%4];" \
                 : "=r"(r0), "=r"(r1), "=r"(r2), "=r"(r3) : "r"(addr))

#define MMA_16816(c, a0, a1, a2, a3, b0, b1) \
    asm volatile("mma.sync.aligned.m16n8k16.row.col.f32.f16.f16.f32 " \
                 "{%0,%1,%2,%3}, {%4,%5,%6,%7}, {%8,%9}, {%0,%1,%2,%3};" \
                 : "+f"((c)[0]), "+f"((c)[1]), "+f"((c)[2]), "+f"((c)[3]) \
                 : "r"(a0), "r"(a1), "r"(a2), "r"(a3), "r"(b0), "r"(b1))

__global__ void __launch_bounds__(256, 2) gemm_kernel(float* __restrict__ out) {
    extern __shared__ __align__(128) char smem[];
    uint32_t sb = smem_u32(smem);
    int tid = threadIdx.x, wid = tid >> 5, lane = tid & 31;

    // GROUP_M=16 tile ordering for L2 reuse
    constexpr int GROUP_M = 16;
    int pid = blockIdx.x;
    int group_size = GROUP_M * TN_TILES;
    int group_id = pid / group_size;
    int pid_m = group_id * GROUP_M + (pid % GROUP_M);
    int pid_n = (pid % group_size) / GROUP_M;
    int m0 = pid_m * BM, n0 = pid_n * BN;

    // warp tile: 32 (m) x 64 (n); warps 4 x 2
    int wm = wid & 3, wn = wid >> 2;
    int m0w = wm * 32, n0w = wn * 64;

    // --- cp.async source/dest precompute: each thread owns 2 chunks per tile ---
    // chunk c in [0,512): row = c>>2, col16 = c&3 ; thread does c = tid, tid+256
    int r0c = tid >> 2, c0c = tid & 3;           // rows 0..63
    int r1c = r0c + 64;                          // rows 64..127
    const __half* gA0 = &g_Ah[(size_t)(m0 + r0c) * K_DIM + c0c * 8];
    const __half* gA1 = &g_Ah[(size_t)(m0 + r1c) * K_DIM + c0c * 8];
    const __half* gB0 = &g_Wt[(size_t)(n0 + r0c) * K_DIM + c0c * 8];
    const __half* gB1 = &g_Wt[(size_t)(n0 + r1c) * K_DIM + c0c * 8];
    uint32_t sA0 = sb + r0c * ROW_BYTES + c0c * 16;
    uint32_t sA1 = sb + r1c * ROW_BYTES + c0c * 16;
    uint32_t sB0 = sb + SB_OFF + r0c * ROW_BYTES + c0c * 16;
    uint32_t sB1 = sb + SB_OFF + r1c * ROW_BYTES + c0c * 16;

    // --- ldmatrix per-lane addresses (stage-relative) ---
    int lrow = lane & 15;          // matrix row within 16
    int lcol8 = lane >> 4;         // 0/1 -> k offset 0/8 within k16
    uint32_t aAddrBase = sb + (m0w + lrow) * ROW_BYTES + lcol8 * 16;
    uint32_t bAddrBase = sb + SB_OFF + (n0w + lrow) * ROW_BYTES + lcol8 * 16;

    float acc[2][8][4];
#pragma unroll
    for (int mt = 0; mt < 2; mt++)
#pragma unroll
        for (int nt = 0; nt < 8; nt++)
#pragma unroll
            for (int j = 0; j < 4; j++) acc[mt][nt][j] = 0.f;

    // --- prologue: stages 0..2 ---
#pragma unroll
    for (int s = 0; s < STAGES - 1; s++) {
        int koff = s * BK;   // halfs
        uint32_t so = s * TILE_STAGE_BYTES;
        CP_ASYNC_16(sA0 + so, gA0 + koff);
        CP_ASYNC_16(sA1 + so, gA1 + koff);
        CP_ASYNC_16(sB0 + so, gB0 + koff);
        CP_ASYNC_16(sB1 + so, gB1 + koff);
        CP_ASYNC_COMMIT();
    }

    for (int kt = 0; kt < KITERS; kt++) {
        CP_ASYNC_WAIT2();
        __syncthreads();

        // issue stage kt+3 into slot (kt+3)%4 (slot (kt-1)%4, consumed last iter)
        if (kt + STAGES - 1 < KITERS) {
            int s = (kt + STAGES - 1) & (STAGES - 1);
            int koff = (kt + STAGES - 1) * BK;
            uint32_t so = s * TILE_STAGE_BYTES;
            CP_ASYNC_16(sA0 + so, gA0 + koff);
            CP_ASYNC_16(sA1 + so, gA1 + koff);
            CP_ASYNC_16(sB0 + so, gB0 + koff);
            CP_ASYNC_16(sB1 + so, gB1 + koff);
            CP_ASYNC_COMMIT();
        } else {
            CP_ASYNC_COMMIT();   // keep group accounting uniform
        }

        uint32_t so = (kt & (STAGES - 1)) * TILE_STAGE_BYTES;
#pragma unroll
        for (int ks = 0; ks < 2; ks++) {
            uint32_t kOff = ks * 32;   // 16 halfs = 32 bytes
            uint32_t a_frag[2][4];
#pragma unroll
            for (int mt = 0; mt < 2; mt++)
                LDSM_X4(a_frag[mt][0], a_frag[mt][1], a_frag[mt][2], a_frag[mt][3],
                        aAddrBase + so + mt * 16 * ROW_BYTES + kOff);
#pragma unroll
            for (int nq = 0; nq < 4; nq++) {     // 16 n per ldmatrix.x4
                uint32_t b0, b1, b2, b3;
                LDSM_X4(b0, b1, b2, b3, bAddrBase + so + nq * 16 * ROW_BYTES + kOff);
                // n-tile 2*nq   -> frags {b0, b2}; n-tile 2*nq+1 -> {b1, b3}
#pragma unroll
                for (int mt = 0; mt < 2; mt++) {
                    MMA_16816(acc[mt][2 * nq], a_frag[mt][0], a_frag[mt][1],
                              a_frag[mt][2], a_frag[mt][3], b0, b2);
                    MMA_16816(acc[mt][2 * nq + 1], a_frag[mt][0], a_frag[mt][1],
                              a_frag[mt][2], a_frag[mt][3], b1, b3);
                }
            }
        }
    }

    // --- epilogue ---
    int gq = lane >> 2, t4 = lane & 3;
#pragma unroll
    for (int mt = 0; mt < 2; mt++) {
        int mrow0 = m0 + m0w + mt * 16 + gq;
#pragma unroll
        for (int nt = 0; nt < 8; nt++) {
            int ncol = n0 + n0w + nt * 8 + t4 * 2;
            float2 v0 = make_float2(acc[mt][nt][0], acc[mt][nt][1]);
            float2 v1 = make_float2(acc[mt][nt][2], acc[mt][nt][3]);
            *reinterpret_cast<float2*>(&out[(size_t)mrow0 * N_DIM + ncol]) = v0;
            *reinterpret_cast<float2*>(&out[(size_t)(mrow0 + 8) * N_DIM + ncol]) = v1;
        }
    }
}

// ---------------- host launch ----------------------------------------------
extern "C" void kernel_launch(void* const* d_in, const int* in_sizes, int n_in,
                              void* d_out, int out_size) {
    const float* A = (const float*)d_in[0];
    const int*   W = (const int*)d_in[1];
    const float* S = (const float*)d_in[2];
    const int*   Z = (const int*)d_in[3];
    float* out = (float*)d_out;

    cudaFuncSetAttribute(gemm_kernel, cudaFuncAttributeMaxDynamicSharedMemorySize, GEMM_SMEM);

    convert_a_kernel<<<((size_t)M_DIM * K_DIM / 4) / 256, 256>>>(A);
    dequant_w_kernel<<<dim3(K_DIM / 64, N_DIM / 32), 256>>>(W, S, Z);
    gemm_kernel<<<TM_TILES * TN_TILES, 256, GEMM_SMEM>>>(out);
}